// round 3
// baseline (speedup 1.0000x reference)
#include <cuda_runtime.h>
#include <cstdint>

// Problem constants: N=50000, E=640000, D=H=128, OUT=32
#define MAXN 50000
#define MAXE 640000

typedef unsigned long long ull;

// Scratch (device globals — no allocation allowed)
__device__ float g_W3[128 * 512];     // [Wp | Wp@WmA | Wp@WmB | Wp@WuA]
__device__ float g_b3[512];           // [bp | bp@WmA | bp@WmB+bm | bp@WuA]
__device__ float g_Y[MAXN * 512];     // per node: h0 | a | b | c
__device__ float g_upd[MAXN * 128];   // pooled @ WuB + bu
__device__ float g_pool[MAXN * 128];  // segment sums
__device__ float g_cnt[MAXN];         // segment counts
__device__ float g_gsum[128];         // graph-level sum of normalized hn

// ---------------------------------------------------------------------------
__global__ void k_zero(int n) {
    int i = blockIdx.x * blockDim.x + threadIdx.x;
    int np = n * 128;
    int total = np + n + 128;
    if (i >= total) return;
    if (i < np)            g_pool[i] = 0.f;
    else if (i < np + n)   g_cnt[i - np] = 0.f;
    else                   g_gsum[i - np - n] = 0.f;
}

// ---------------------------------------------------------------------------
// Build combined weights/biases: W3 = [Wp | Wp@WmA | Wp@WmB | Wp@WuA]
// ---------------------------------------------------------------------------
__global__ void k_prep(const float* __restrict__ Wp, const float* __restrict__ bp,
                       const float* __restrict__ Wm, const float* __restrict__ bm,
                       const float* __restrict__ Wu) {
    int idx = blockIdx.x * blockDim.x + threadIdx.x;
    if (idx < 128 * 512) {
        int i = idx >> 9;
        int j = idx & 511;
        int blk = j >> 7, jj = j & 127;
        float v;
        if (blk == 0) {
            v = Wp[i * 128 + jj];
        } else {
            const float* M = (blk == 1) ? Wm : (blk == 2 ? Wm + 16384 : Wu);
            float s = 0.f;
            for (int k = 0; k < 128; k++) s += Wp[i * 128 + k] * M[k * 128 + jj];
            v = s;
        }
        g_W3[idx] = v;
    }
    if (idx < 512) {
        int blk = idx >> 7, jj = idx & 127;
        float v;
        if (blk == 0) {
            v = bp[jj];
        } else {
            const float* M = (blk == 1) ? Wm : (blk == 2 ? Wm + 16384 : Wu);
            float s = (blk == 2) ? bm[jj] : 0.f;
            for (int k = 0; k < 128; k++) s += bp[k] * M[k * 128 + jj];
            v = s;
        }
        g_b3[idx] = v;
    }
}

// ---------------------------------------------------------------------------
// f32x2 tiled GEMM: 128x128 tile, 256 threads, 8x8 per thread via fma.rn.f32x2.
// mode 0: g_Y[n,512] = x[n,128] @ g_W3[128,512] + g_b3
// mode 1: g_upd[n,128] = (g_pool/max(cnt,1))[n,128] @ Wext[128,128] + biasExt
// A stored duplicated in smem: As2[k][m] = (a, a) so one fma.f32x2 does 2 cols.
// ---------------------------------------------------------------------------
__global__ void __launch_bounds__(256) k_gemm(const float* __restrict__ Xext,
                                              const float* __restrict__ Wext,
                                              const float* __restrict__ biasExt,
                                              int n, int mode) {
    __shared__ __align__(16) float2 As2[16][128];
    __shared__ __align__(16) float  Bs[16][128];

    const float* X    = mode ? g_pool : Xext;
    const float* W    = mode ? Wext   : g_W3;
    const float* bias = mode ? biasExt : g_b3;
    float* Yout       = mode ? g_upd  : g_Y;
    const int p4      = mode ? 32 : 128;   // W row pitch and out row pitch, float4

    const int tid = threadIdx.x;
    const int tx = tid & 15;       // col group: cols tx*8 .. tx*8+7
    const int ty = tid >> 4;       // row group: rows ty*8 .. ty*8+7
    const int rowBase = blockIdx.y * 128;
    const int cb4 = blockIdx.x * 32;   // column base in float4 units

    // A loader mapping: rows arow, arow+64; float4 column af4
    const int arow = tid >> 2;
    const int af4  = tid & 3;
    // B loader mapping: k rows bk, bk+8; float4 column bc4
    const int bk  = tid >> 5;
    const int bc4 = tid & 31;

    // Per-row reciprocal counts (mode 1), hoisted
    float rc0 = 1.f, rc1 = 1.f;
    int ar0 = rowBase + arow, ar1 = rowBase + arow + 64;
    if (mode) {
        if (ar0 < n) rc0 = 1.0f / fmaxf(g_cnt[ar0], 1.0f);
        if (ar1 < n) rc1 = 1.0f / fmaxf(g_cnt[ar1], 1.0f);
    }

    ull acc[8][4];
    #pragma unroll
    for (int r = 0; r < 8; r++)
        #pragma unroll
        for (int c = 0; c < 4; c++) acc[r][c] = 0ull;

    float4 ra[2], rb[2];
    // Prefetch chunk 0
    {
        float4 z = make_float4(0.f, 0.f, 0.f, 0.f);
        ra[0] = (ar0 < n) ? ((const float4*)X)[(size_t)ar0 * 32 + af4] : z;
        ra[1] = (ar1 < n) ? ((const float4*)X)[(size_t)ar1 * 32 + af4] : z;
        rb[0] = ((const float4*)W)[(size_t)(bk    ) * p4 + cb4 + bc4];
        rb[1] = ((const float4*)W)[(size_t)(bk + 8) * p4 + cb4 + bc4];
    }

    for (int kt = 0; kt < 8; kt++) {
        // Stage registers -> smem
        if (mode) {
            ra[0].x *= rc0; ra[0].y *= rc0; ra[0].z *= rc0; ra[0].w *= rc0;
            ra[1].x *= rc1; ra[1].y *= rc1; ra[1].z *= rc1; ra[1].w *= rc1;
        }
        #pragma unroll
        for (int it = 0; it < 2; it++) {
            int m = arow + it * 64;
            float4 v = ra[it];
            As2[af4 * 4 + 0][m] = make_float2(v.x, v.x);
            As2[af4 * 4 + 1][m] = make_float2(v.y, v.y);
            As2[af4 * 4 + 2][m] = make_float2(v.z, v.z);
            As2[af4 * 4 + 3][m] = make_float2(v.w, v.w);
        }
        *(float4*)&Bs[bk    ][bc4 * 4] = rb[0];
        *(float4*)&Bs[bk + 8][bc4 * 4] = rb[1];
        __syncthreads();

        // Prefetch next chunk (latency hidden behind compute)
        if (kt < 7) {
            float4 z = make_float4(0.f, 0.f, 0.f, 0.f);
            ra[0] = (ar0 < n) ? ((const float4*)X)[(size_t)ar0 * 32 + (kt + 1) * 4 + af4] : z;
            ra[1] = (ar1 < n) ? ((const float4*)X)[(size_t)ar1 * 32 + (kt + 1) * 4 + af4] : z;
            rb[0] = ((const float4*)W)[(size_t)((kt + 1) * 16 + bk    ) * p4 + cb4 + bc4];
            rb[1] = ((const float4*)W)[(size_t)((kt + 1) * 16 + bk + 8) * p4 + cb4 + bc4];
        }

        #pragma unroll
        for (int k = 0; k < 16; k++) {
            ull a[8], b[4];
            longlong2 p0 = *(longlong2*)&As2[k][ty * 8 + 0];
            longlong2 p1 = *(longlong2*)&As2[k][ty * 8 + 2];
            longlong2 p2 = *(longlong2*)&As2[k][ty * 8 + 4];
            longlong2 p3 = *(longlong2*)&As2[k][ty * 8 + 6];
            a[0] = (ull)p0.x; a[1] = (ull)p0.y;
            a[2] = (ull)p1.x; a[3] = (ull)p1.y;
            a[4] = (ull)p2.x; a[5] = (ull)p2.y;
            a[6] = (ull)p3.x; a[7] = (ull)p3.y;
            longlong2 q0 = *(longlong2*)&Bs[k][tx * 8];
            longlong2 q1 = *(longlong2*)&Bs[k][tx * 8 + 4];
            b[0] = (ull)q0.x; b[1] = (ull)q0.y;
            b[2] = (ull)q1.x; b[3] = (ull)q1.y;
            #pragma unroll
            for (int r = 0; r < 8; r++) {
                #pragma unroll
                for (int c = 0; c < 4; c++) {
                    asm("fma.rn.f32x2 %0, %1, %2, %0;"
                        : "+l"(acc[r][c]) : "l"(a[r]), "l"(b[c]));
                }
            }
        }
        __syncthreads();
    }

    // Epilogue: bias + store
    float4 bv0 = ((const float4*)bias)[cb4 + tx * 2];
    float4 bv1 = ((const float4*)bias)[cb4 + tx * 2 + 1];
    float4* outp = (float4*)Yout;
    #pragma unroll
    for (int r = 0; r < 8; r++) {
        int row = rowBase + ty * 8 + r;
        if (row < n) {
            float2 f0 = *(float2*)&acc[r][0];
            float2 f1 = *(float2*)&acc[r][1];
            float2 f2 = *(float2*)&acc[r][2];
            float2 f3 = *(float2*)&acc[r][3];
            float4 o0 = make_float4(f0.x + bv0.x, f0.y + bv0.y, f1.x + bv0.z, f1.y + bv0.w);
            float4 o1 = make_float4(f2.x + bv1.x, f2.y + bv1.y, f3.x + bv1.z, f3.y + bv1.w);
            outp[(size_t)row * p4 + cb4 + tx * 2]     = o0;
            outp[(size_t)row * p4 + cb4 + tx * 2 + 1] = o1;
        }
    }
}

// ---------------------------------------------------------------------------
// Edge kernel: one warp per edge. msg = relu(a[src]+b[dst]); red.v4 into pool.
// ---------------------------------------------------------------------------
__global__ void __launch_bounds__(256) k_edge(const int* __restrict__ src,
                                              const int* __restrict__ dst, int e) {
    int wid = (blockIdx.x * blockDim.x + threadIdx.x) >> 5;
    if (wid >= e) return;
    int lane = threadIdx.x & 31;
    int s = __ldg(src + wid);
    int d = __ldg(dst + wid);

    const float4* Y4 = (const float4*)g_Y;
    float4 va = __ldg(Y4 + (size_t)s * 128 + 32 + lane);   // a block
    float4 vb = __ldg(Y4 + (size_t)d * 128 + 64 + lane);   // b block
    float4 m;
    m.x = fmaxf(va.x + vb.x, 0.f);
    m.y = fmaxf(va.y + vb.y, 0.f);
    m.z = fmaxf(va.z + vb.z, 0.f);
    m.w = fmaxf(va.w + vb.w, 0.f);

    float* p = g_pool + (size_t)d * 128 + lane * 4;
    asm volatile("red.global.add.v4.f32 [%0], {%1,%2,%3,%4};"
                 :: "l"(p), "f"(m.x), "f"(m.y), "f"(m.z), "f"(m.w) : "memory");
    if (lane == 0) atomicAdd(g_cnt + d, 1.0f);
}

// ---------------------------------------------------------------------------
// Fused relu + LayerNorm + graph mean-pool partial sums. Warp per row.
// ---------------------------------------------------------------------------
__global__ void __launch_bounds__(256) k_ln(const float* __restrict__ gamma,
                                            const float* __restrict__ beta, int n) {
    __shared__ float sacc[8][128];
    int lane = threadIdx.x & 31;
    int w = threadIdx.x >> 5;
    int gw = blockIdx.x * 8 + w;
    int nw = gridDim.x * 8;

    float4 ga = ((const float4*)gamma)[lane];
    float4 be = ((const float4*)beta)[lane];
    float ax = 0.f, ay = 0.f, az = 0.f, aw = 0.f;

    for (int row = gw; row < n; row += nw) {
        const float4* yr = ((const float4*)g_Y) + (size_t)row * 128;
        float4 h0 = __ldg(yr + lane);        // h0 block
        float4 cv = __ldg(yr + 96 + lane);   // c  block
        float4 up = __ldg(((const float4*)g_upd) + (size_t)row * 32 + lane);
        float vx = fmaxf(h0.x + cv.x + up.x, 0.f);
        float vy = fmaxf(h0.y + cv.y + up.y, 0.f);
        float vz = fmaxf(h0.z + cv.z + up.z, 0.f);
        float vw = fmaxf(h0.w + cv.w + up.w, 0.f);

        float s1 = vx + vy + vz + vw;
        float s2 = vx * vx + vy * vy + vz * vz + vw * vw;
        #pragma unroll
        for (int o = 16; o > 0; o >>= 1) {
            s1 += __shfl_xor_sync(0xFFFFFFFFu, s1, o);
            s2 += __shfl_xor_sync(0xFFFFFFFFu, s2, o);
        }
        float mu  = s1 * (1.f / 128.f);
        float var = s2 * (1.f / 128.f) - mu * mu;
        float is  = rsqrtf(var + 1e-6f);
        ax += (vx - mu) * is * ga.x + be.x;
        ay += (vy - mu) * is * ga.y + be.y;
        az += (vz - mu) * is * ga.z + be.z;
        aw += (vw - mu) * is * ga.w + be.w;
    }

    sacc[w][lane * 4 + 0] = ax;
    sacc[w][lane * 4 + 1] = ay;
    sacc[w][lane * 4 + 2] = az;
    sacc[w][lane * 4 + 3] = aw;
    __syncthreads();
    int t = threadIdx.x;
    if (t < 128) {
        float s = 0.f;
        #pragma unroll
        for (int ww = 0; ww < 8; ww++) s += sacc[ww][t];
        atomicAdd(&g_gsum[t], s);
    }
}

// ---------------------------------------------------------------------------
__global__ void k_final(const float* __restrict__ Wd, const float* __restrict__ bd,
                        float* __restrict__ out, int n) {
    int o = threadIdx.x;
    if (o >= 32) return;
    float s = 0.f;
    #pragma unroll
    for (int c = 0; c < 128; c++) s += g_gsum[c] * Wd[c * 32 + o];
    out[o] = s / (float)n + bd[o];
}

// ---------------------------------------------------------------------------
extern "C" void kernel_launch(void* const* d_in, const int* in_sizes, int n_in,
                              void* d_out, int out_size) {
    const float* x     = (const float*)d_in[0];
    const int*   esrc  = (const int*)d_in[1];
    const int*   edst  = (const int*)d_in[2];
    const float* Wp    = (const float*)d_in[3];
    const float* bp    = (const float*)d_in[4];
    const float* Wm    = (const float*)d_in[5];
    const float* bm    = (const float*)d_in[6];
    const float* Wu    = (const float*)d_in[7];
    const float* bu    = (const float*)d_in[8];
    const float* gamma = (const float*)d_in[9];
    const float* beta  = (const float*)d_in[10];
    const float* Wd    = (const float*)d_in[11];
    const float* bd    = (const float*)d_in[12];
    float* out = (float*)d_out;

    int n = in_sizes[0] / 128;
    int e = in_sizes[1];
    int rb = (n + 127) / 128;

    k_zero<<<(n * 129 + 128 + 255) / 256, 256>>>(n);
    k_prep<<<256, 256>>>(Wp, bp, Wm, bm, Wu);
    // Y = x @ W3 + b3  -> h0 | a | b | c
    k_gemm<<<dim3(4, rb), 256>>>(x, nullptr, nullptr, n, 0);
    // scatter edge messages
    k_edge<<<(e + 7) / 8, 256>>>(esrc, edst, e);
    // upd = pooled @ WuB + bu
    k_gemm<<<dim3(1, rb), 256>>>(nullptr, Wu + 16384, bu, n, 1);
    // relu + LN + graph pool
    k_ln<<<1024, 256>>>(gamma, beta, n);
    k_final<<<1, 32>>>(Wd, bd, out, n);
}

// round 5
// speedup vs baseline: 1.0577x; 1.0577x over previous
#include <cuda_runtime.h>
#include <mma.h>
#include <cstdint>

using namespace nvcuda;

// Problem constants: N=50000, E=640000, D=H=128, OUT=32
#define MAXN 50000
#define MAXE 640000

// Scratch (device globals — no allocation allowed)
__device__ float g_W3[128 * 512];     // [Wp | Wp@WmA | Wp@WmB | Wp@WuA]
__device__ float g_b3[512];           // [bp | bp@WmA | bp@WmB+bm | bp@WuA]
__device__ float g_Y[MAXN * 512];     // per node: h0 | a | b | c
__device__ float g_upd[MAXN * 128];   // pooled @ WuB + bu
__device__ float g_pool[MAXN * 128];  // segment sums
__device__ float g_cnt[MAXN];         // segment counts
__device__ float g_gsum[128];         // graph-level sum of normalized hn

__device__ __forceinline__ float f2tf32f(float f) {
    uint32_t u;
    asm("cvt.rna.tf32.f32 %0, %1;" : "=r"(u) : "f"(f));
    return __uint_as_float(u);
}

// ---------------------------------------------------------------------------
__global__ void k_zero(int n) {
    int i = blockIdx.x * blockDim.x + threadIdx.x;
    int np = n * 128;
    int total = np + n + 128;
    if (i >= total) return;
    if (i < np)            g_pool[i] = 0.f;
    else if (i < np + n)   g_cnt[i - np] = 0.f;
    else                   g_gsum[i - np - n] = 0.f;
}

// ---------------------------------------------------------------------------
// Build combined weights/biases: W3 = [Wp | Wp@WmA | Wp@WmB | Wp@WuA]
// (fp32 exact; done once per launch, tiny)
// ---------------------------------------------------------------------------
__global__ void k_prep(const float* __restrict__ Wp, const float* __restrict__ bp,
                       const float* __restrict__ Wm, const float* __restrict__ bm,
                       const float* __restrict__ Wu) {
    int idx = blockIdx.x * blockDim.x + threadIdx.x;
    if (idx < 128 * 512) {
        int i = idx >> 9;
        int j = idx & 511;
        int blk = j >> 7, jj = j & 127;
        float v;
        if (blk == 0) {
            v = Wp[i * 128 + jj];
        } else {
            const float* M = (blk == 1) ? Wm : (blk == 2 ? Wm + 16384 : Wu);
            float s = 0.f;
            for (int k = 0; k < 128; k++) s += Wp[i * 128 + k] * M[k * 128 + jj];
            v = s;
        }
        g_W3[idx] = v;
    }
    if (idx < 512) {
        int blk = idx >> 7, jj = idx & 127;
        float v;
        if (blk == 0) {
            v = bp[jj];
        } else {
            const float* M = (blk == 1) ? Wm : (blk == 2 ? Wm + 16384 : Wu);
            float s = (blk == 2) ? bm[jj] : 0.f;
            for (int k = 0; k < 128; k++) s += bp[k] * M[k * 128 + jj];
            v = s;
        }
        g_b3[idx] = v;
    }
}

// ---------------------------------------------------------------------------
// wmma tf32 GEMM: CTA = 128x128 output tile, K=128 resident in smem.
// mode 0: g_Y[n,512] = x[n,128] @ g_W3[128,512] + g_b3     (grid.x = 4)
// mode 1: g_upd[n,128] = (g_pool/max(cnt,1)) @ Wext + bias (grid.x = 1)
// 8 warps, 4x2 layout, each warp 32x64 (2 m16 x 4 n16 frags), 16 k8 steps.
// ---------------------------------------------------------------------------
#define LDA 136
#define SMA_FLOATS (128 * LDA)
#define GSM_SZ (2 * SMA_FLOATS * 4)

__global__ void __launch_bounds__(256) k_gemm_w(const float* __restrict__ Xext,
                                                const float* __restrict__ Wext,
                                                const float* __restrict__ biasExt,
                                                int n, int mode) {
    extern __shared__ __align__(16) float smw[];
    float* As = smw;                 // [128][LDA]  (A, then reused for C)
    float* Bs = smw + SMA_FLOATS;    // [128][LDA]  (B: rows k, cols n)

    const float* X    = mode ? g_pool : Xext;
    const float* W    = mode ? Wext   : g_W3;
    const float* bias = mode ? biasExt : g_b3;
    float* Yout       = mode ? g_upd  : g_Y;
    const int wp4     = mode ? 32 : 128;   // W row pitch (float4)
    const int op4     = mode ? 32 : 128;   // out row pitch (float4)
    const int rowBase = blockIdx.y * 128;
    const int cb4     = blockIdx.x * 32;   // column base (float4)

    const int tid = threadIdx.x;
    const int wid = tid >> 5;

    // ---- Fill A (tf32-rounded, mode-1 scaled) and B (tf32-rounded) ----
    const float4* X4 = (const float4*)X;
    const float4* W4 = (const float4*)W;
    for (int i = tid; i < 4096; i += 256) {
        int m = i >> 5, k4 = i & 31;
        int row = rowBase + m;
        float4 v = make_float4(0.f, 0.f, 0.f, 0.f);
        if (row < n) {
            v = X4[(size_t)row * 32 + k4];
            if (mode) {
                float rc = 1.0f / fmaxf(g_cnt[row], 1.0f);
                v.x *= rc; v.y *= rc; v.z *= rc; v.w *= rc;
            }
        }
        float4 t = make_float4(f2tf32f(v.x), f2tf32f(v.y), f2tf32f(v.z), f2tf32f(v.w));
        *(float4*)&As[m * LDA + k4 * 4] = t;

        // B: row k = m, cols
        float4 w = W4[(size_t)m * wp4 + cb4 + k4];
        float4 tw = make_float4(f2tf32f(w.x), f2tf32f(w.y), f2tf32f(w.z), f2tf32f(w.w));
        *(float4*)&Bs[m * LDA + k4 * 4] = tw;
    }
    __syncthreads();

    // ---- MMA main loop ----
    const int wrow = (wid & 3) * 32;   // warp row base within tile
    const int wcol = (wid >> 2) * 64;  // warp col base within tile

    wmma::fragment<wmma::accumulator, 16, 16, 8, float> acc[2][4];
    #pragma unroll
    for (int r = 0; r < 2; r++)
        #pragma unroll
        for (int c = 0; c < 4; c++) wmma::fill_fragment(acc[r][c], 0.0f);

    #pragma unroll
    for (int kk = 0; kk < 16; kk++) {
        wmma::fragment<wmma::matrix_a, 16, 16, 8, wmma::precision::tf32, wmma::row_major> af[2];
        wmma::fragment<wmma::matrix_b, 16, 16, 8, wmma::precision::tf32, wmma::row_major> bf[4];
        #pragma unroll
        for (int r = 0; r < 2; r++)
            wmma::load_matrix_sync(af[r], &As[(wrow + r * 16) * LDA + kk * 8], LDA);
        #pragma unroll
        for (int c = 0; c < 4; c++)
            wmma::load_matrix_sync(bf[c], &Bs[(kk * 8) * LDA + wcol + c * 16], LDA);
        #pragma unroll
        for (int r = 0; r < 2; r++)
            #pragma unroll
            for (int c = 0; c < 4; c++)
                wmma::mma_sync(acc[r][c], af[r], bf[c], acc[r][c]);
    }

    // ---- Epilogue: stage C into As, then bias + vector store ----
    __syncthreads();
    #pragma unroll
    for (int r = 0; r < 2; r++)
        #pragma unroll
        for (int c = 0; c < 4; c++)
            wmma::store_matrix_sync(&As[(wrow + r * 16) * LDA + wcol + c * 16],
                                    acc[r][c], LDA, wmma::mem_row_major);
    __syncthreads();

    const float4* b4 = (const float4*)bias;
    float4* out4 = (float4*)Yout;
    for (int i = tid; i < 4096; i += 256) {
        int m = i >> 5, c4 = i & 31;
        int row = rowBase + m;
        if (row < n) {
            float4 v = *(float4*)&As[m * LDA + c4 * 4];
            float4 bv = b4[cb4 + c4];
            v.x += bv.x; v.y += bv.y; v.z += bv.z; v.w += bv.w;
            out4[(size_t)row * op4 + cb4 + c4] = v;
        }
    }
}

// ---------------------------------------------------------------------------
// Edge kernel: one warp per edge. msg = relu(a[src]+b[dst]); red.v4 into pool.
// ---------------------------------------------------------------------------
__global__ void __launch_bounds__(256) k_edge(const int* __restrict__ src,
                                              const int* __restrict__ dst, int e) {
    int wid = (blockIdx.x * blockDim.x + threadIdx.x) >> 5;
    if (wid >= e) return;
    int lane = threadIdx.x & 31;
    int s = __ldg(src + wid);
    int d = __ldg(dst + wid);

    const float4* Y4 = (const float4*)g_Y;
    float4 va = __ldg(Y4 + (size_t)s * 128 + 32 + lane);   // a block
    float4 vb = __ldg(Y4 + (size_t)d * 128 + 64 + lane);   // b block
    float4 m;
    m.x = fmaxf(va.x + vb.x, 0.f);
    m.y = fmaxf(va.y + vb.y, 0.f);
    m.z = fmaxf(va.z + vb.z, 0.f);
    m.w = fmaxf(va.w + vb.w, 0.f);

    float* p = g_pool + (size_t)d * 128 + lane * 4;
    asm volatile("red.global.add.v4.f32 [%0], {%1,%2,%3,%4};"
                 :: "l"(p), "f"(m.x), "f"(m.y), "f"(m.z), "f"(m.w) : "memory");
    if (lane == 0) atomicAdd(g_cnt + d, 1.0f);
}

// ---------------------------------------------------------------------------
// Fused relu + LayerNorm + graph mean-pool partial sums. Warp per row.
// ---------------------------------------------------------------------------
__global__ void __launch_bounds__(256) k_ln(const float* __restrict__ gamma,
                                            const float* __restrict__ beta, int n) {
    __shared__ float sacc[8][128];
    int lane = threadIdx.x & 31;
    int w = threadIdx.x >> 5;
    int gw = blockIdx.x * 8 + w;
    int nw = gridDim.x * 8;

    float4 ga = ((const float4*)gamma)[lane];
    float4 be = ((const float4*)beta)[lane];
    float ax = 0.f, ay = 0.f, az = 0.f, aw = 0.f;

    for (int row = gw; row < n; row += nw) {
        const float4* yr = ((const float4*)g_Y) + (size_t)row * 128;
        float4 h0 = __ldg(yr + lane);        // h0 block
        float4 cv = __ldg(yr + 96 + lane);   // c  block
        float4 up = __ldg(((const float4*)g_upd) + (size_t)row * 32 + lane);
        float vx = fmaxf(h0.x + cv.x + up.x, 0.f);
        float vy = fmaxf(h0.y + cv.y + up.y, 0.f);
        float vz = fmaxf(h0.z + cv.z + up.z, 0.f);
        float vw = fmaxf(h0.w + cv.w + up.w, 0.f);

        float s1 = vx + vy + vz + vw;
        float s2 = vx * vx + vy * vy + vz * vz + vw * vw;
        #pragma unroll
        for (int o = 16; o > 0; o >>= 1) {
            s1 += __shfl_xor_sync(0xFFFFFFFFu, s1, o);
            s2 += __shfl_xor_sync(0xFFFFFFFFu, s2, o);
        }
        float mu  = s1 * (1.f / 128.f);
        float var = s2 * (1.f / 128.f) - mu * mu;
        float is  = rsqrtf(var + 1e-6f);
        ax += (vx - mu) * is * ga.x + be.x;
        ay += (vy - mu) * is * ga.y + be.y;
        az += (vz - mu) * is * ga.z + be.z;
        aw += (vw - mu) * is * ga.w + be.w;
    }

    sacc[w][lane * 4 + 0] = ax;
    sacc[w][lane * 4 + 1] = ay;
    sacc[w][lane * 4 + 2] = az;
    sacc[w][lane * 4 + 3] = aw;
    __syncthreads();
    int t = threadIdx.x;
    if (t < 128) {
        float s = 0.f;
        #pragma unroll
        for (int ww = 0; ww < 8; ww++) s += sacc[ww][t];
        atomicAdd(&g_gsum[t], s);
    }
}

// ---------------------------------------------------------------------------
__global__ void k_final(const float* __restrict__ Wd, const float* __restrict__ bd,
                        float* __restrict__ out, int n) {
    int o = threadIdx.x;
    if (o >= 32) return;
    float s = 0.f;
    #pragma unroll
    for (int c = 0; c < 128; c++) s += g_gsum[c] * Wd[c * 32 + o];
    out[o] = s / (float)n + bd[o];
}

// ---------------------------------------------------------------------------
extern "C" void kernel_launch(void* const* d_in, const int* in_sizes, int n_in,
                              void* d_out, int out_size) {
    const float* x     = (const float*)d_in[0];
    const int*   esrc  = (const int*)d_in[1];
    const int*   edst  = (const int*)d_in[2];
    const float* Wp    = (const float*)d_in[3];
    const float* bp    = (const float*)d_in[4];
    const float* Wm    = (const float*)d_in[5];
    const float* bm    = (const float*)d_in[6];
    const float* Wu    = (const float*)d_in[7];
    const float* bu    = (const float*)d_in[8];
    const float* gamma = (const float*)d_in[9];
    const float* beta  = (const float*)d_in[10];
    const float* Wd    = (const float*)d_in[11];
    const float* bd    = (const float*)d_in[12];
    float* out = (float*)d_out;

    int n = in_sizes[0] / 128;
    int e = in_sizes[1];
    int rb = (n + 127) / 128;

    static bool attr_done = false;
    if (!attr_done) {
        cudaFuncSetAttribute(k_gemm_w, cudaFuncAttributeMaxDynamicSharedMemorySize, GSM_SZ);
        attr_done = true;
    }

    k_zero<<<(n * 129 + 128 + 255) / 256, 256>>>(n);
    k_prep<<<256, 256>>>(Wp, bp, Wm, bm, Wu);
    // Y = x @ W3 + b3  -> h0 | a | b | c
    k_gemm_w<<<dim3(4, rb), 256, GSM_SZ>>>(x, nullptr, nullptr, n, 0);
    // scatter edge messages
    k_edge<<<(e + 7) / 8, 256>>>(esrc, edst, e);
    // upd = pooled @ WuB + bu
    k_gemm_w<<<dim3(1, rb), 256, GSM_SZ>>>(nullptr, Wu + 16384, bu, n, 1);
    // relu + LN + graph pool
    k_ln<<<1024, 256>>>(gamma, beta, n);
    k_final<<<1, 32>>>(Wd, bd, out, n);
}

// round 6
// speedup vs baseline: 1.8428x; 1.7423x over previous
#include <cuda_runtime.h>
#include <cuda_fp16.h>
#include <mma.h>
#include <cstdint>

using namespace nvcuda;

// Problem constants: N=50000, E=640000, D=H=128, OUT=32
#define MAXN 50000
#define MAXE 640000

// Scratch (device globals — no allocation allowed)
__device__ float g_W3[128 * 512];     // [Wp | Wp@WmA | Wp@WmB | Wp@WuA]
__device__ float g_b3[512];           // [bp | bp@WmA | bp@WmB+bm | bp@WuA]
__device__ float g_Y[MAXN * 512];     // per node: h0 | a | b | c
__device__ float g_upd[MAXN * 128];   // pooled @ WuB + bu
__device__ float g_pool[MAXN * 128];  // pooled mean (mean folded in)
__device__ float g_gsum[128];         // graph-level sum of normalized hn
__device__ int   g_deg[MAXN];         // per-dst degree
__device__ int   g_off[MAXN];         // CSR offsets
__device__ int   g_cur[MAXN];         // scatter cursors
__device__ int   g_elist[MAXE];       // src ids grouped by dst

// ---------------------------------------------------------------------------
__global__ void k_zero(int n) {
    int i = blockIdx.x * blockDim.x + threadIdx.x;
    if (i < n) g_deg[i] = 0;
}

// ---------------------------------------------------------------------------
// Build combined weights/biases: W3 = [Wp | Wp@WmA | Wp@WmB | Wp@WuA]
// ---------------------------------------------------------------------------
__global__ void k_prep(const float* __restrict__ Wp, const float* __restrict__ bp,
                       const float* __restrict__ Wm, const float* __restrict__ bm,
                       const float* __restrict__ Wu) {
    int idx = blockIdx.x * blockDim.x + threadIdx.x;
    if (idx < 128 * 512) {
        int i = idx >> 9;
        int j = idx & 511;
        int blk = j >> 7, jj = j & 127;
        float v;
        if (blk == 0) {
            v = Wp[i * 128 + jj];
        } else {
            const float* M = (blk == 1) ? Wm : (blk == 2 ? Wm + 16384 : Wu);
            float s = 0.f;
            for (int k = 0; k < 128; k++) s += Wp[i * 128 + k] * M[k * 128 + jj];
            v = s;
        }
        g_W3[idx] = v;
    }
    if (idx < 512) {
        int blk = idx >> 7, jj = idx & 127;
        float v;
        if (blk == 0) {
            v = bp[jj];
        } else {
            const float* M = (blk == 1) ? Wm : (blk == 2 ? Wm + 16384 : Wu);
            float s = (blk == 2) ? bm[jj] : 0.f;
            for (int k = 0; k < 128; k++) s += bp[k] * M[k * 128 + jj];
            v = s;
        }
        g_b3[idx] = v;
    }
}

// ---------------------------------------------------------------------------
// fp16 wmma GEMM: CTA = 128x128 output tile, K=128 resident in smem (fp16).
// mode 0: g_Y[n,512] = x @ g_W3 + g_b3        (grid.x = 4)
// mode 1: g_upd[n,128] = g_pool @ Wext + bias (grid.x = 1)
// 8 warps in 4x2 layout; warp tile 32x64 (2x4 m16n16k16 frags), 8 k-steps.
// smem: A fp16 [128][136] (34816B) + B fp16 [128][136]; C fp32 [128][132] overlaps.
// ---------------------------------------------------------------------------
#define LDH 136
#define LDC 132
#define SM_A_BYTES (128 * LDH * 2)
#define GSM_SZ (2 * SM_A_BYTES)

__global__ void __launch_bounds__(256, 2) k_gemm_h(const float* __restrict__ Xext,
                                                   const float* __restrict__ Wext,
                                                   const float* __restrict__ biasExt,
                                                   int n, int mode) {
    extern __shared__ __align__(16) char smw[];
    half*  As = (half*)smw;
    half*  Bs = (half*)(smw + SM_A_BYTES);
    float* Cs = (float*)smw;   // overlaps A+B (used after sync)

    const float* X    = mode ? g_pool : Xext;
    const float* W    = mode ? Wext   : g_W3;
    const float* bias = mode ? biasExt : g_b3;
    float* Yout       = mode ? g_upd  : g_Y;
    const int wp4     = mode ? 32 : 128;   // W row pitch (float4)
    const int op4     = mode ? 32 : 128;   // out row pitch (float4)
    const int rowBase = blockIdx.y * 128;
    const int cb4     = blockIdx.x * 32;   // column base (float4)

    const int tid = threadIdx.x;
    const int wid = tid >> 5;

    // ---- Fill A and B tiles (fp32 -> fp16) ----
    const float4* X4 = (const float4*)X;
    const float4* W4 = (const float4*)W;
    #pragma unroll
    for (int it = 0; it < 16; it++) {
        int i = tid + it * 256;
        int m = i >> 5, c4 = i & 31;
        int row = rowBase + m;
        float4 v = make_float4(0.f, 0.f, 0.f, 0.f);
        if (row < n) v = X4[(size_t)row * 32 + c4];
        half2* da = (half2*)&As[m * LDH + c4 * 4];
        da[0] = __floats2half2_rn(v.x, v.y);
        da[1] = __floats2half2_rn(v.z, v.w);

        float4 w = W4[(size_t)m * wp4 + cb4 + c4];
        half2* db = (half2*)&Bs[m * LDH + c4 * 4];
        db[0] = __floats2half2_rn(w.x, w.y);
        db[1] = __floats2half2_rn(w.z, w.w);
    }
    __syncthreads();

    // ---- MMA main loop ----
    const int wrow = (wid & 3) * 32;
    const int wcol = (wid >> 2) * 64;

    wmma::fragment<wmma::accumulator, 16, 16, 16, float> acc[2][4];
    #pragma unroll
    for (int r = 0; r < 2; r++)
        #pragma unroll
        for (int c = 0; c < 4; c++) wmma::fill_fragment(acc[r][c], 0.0f);

    #pragma unroll
    for (int kk = 0; kk < 8; kk++) {
        wmma::fragment<wmma::matrix_a, 16, 16, 16, half, wmma::row_major> af[2];
        wmma::fragment<wmma::matrix_b, 16, 16, 16, half, wmma::row_major> bf[4];
        #pragma unroll
        for (int r = 0; r < 2; r++)
            wmma::load_matrix_sync(af[r], &As[(wrow + r * 16) * LDH + kk * 16], LDH);
        #pragma unroll
        for (int c = 0; c < 4; c++)
            wmma::load_matrix_sync(bf[c], &Bs[(kk * 16) * LDH + wcol + c * 16], LDH);
        #pragma unroll
        for (int r = 0; r < 2; r++)
            #pragma unroll
            for (int c = 0; c < 4; c++)
                wmma::mma_sync(acc[r][c], af[r], bf[c], acc[r][c]);
    }

    // ---- Epilogue: stage C (fp32) into smem, then bias + vector store ----
    __syncthreads();
    #pragma unroll
    for (int r = 0; r < 2; r++)
        #pragma unroll
        for (int c = 0; c < 4; c++)
            wmma::store_matrix_sync(&Cs[(wrow + r * 16) * LDC + wcol + c * 16],
                                    acc[r][c], LDC, wmma::mem_row_major);
    __syncthreads();

    const float4* b4 = (const float4*)bias;
    float4* out4 = (float4*)Yout;
    #pragma unroll
    for (int it = 0; it < 16; it++) {
        int i = tid + it * 256;
        int m = i >> 5, c4 = i & 31;
        int row = rowBase + m;
        if (row < n) {
            float4 v = *(float4*)&Cs[m * LDC + c4 * 4];
            float4 bv = b4[cb4 + c4];
            v.x += bv.x; v.y += bv.y; v.z += bv.z; v.w += bv.w;
            out4[(size_t)row * op4 + cb4 + c4] = v;
        }
    }
}

// ---------------------------------------------------------------------------
// CSR build: histogram -> single-block scan -> scatter
// ---------------------------------------------------------------------------
__global__ void k_hist(const int* __restrict__ dst, int e) {
    int i = blockIdx.x * blockDim.x + threadIdx.x;
    if (i < e) atomicAdd(&g_deg[dst[i]], 1);
}

__global__ void __launch_bounds__(1024) k_scan(int n) {
    __shared__ int wsum[32];
    int tid = threadIdx.x;
    int lane = tid & 31, wd = tid >> 5;
    int chunk = (n + 1023) / 1024;
    int lo = tid * chunk; if (lo > n) lo = n;
    int hi = lo + chunk;  if (hi > n) hi = n;
    int s = 0;
    for (int i = lo; i < hi; i++) s += g_deg[i];
    int v = s;
    #pragma unroll
    for (int o = 1; o < 32; o <<= 1) {
        int t = __shfl_up_sync(0xFFFFFFFFu, v, o);
        if (lane >= o) v += t;
    }
    if (lane == 31) wsum[wd] = v;
    __syncthreads();
    if (wd == 0) {
        int w = wsum[lane];
        #pragma unroll
        for (int o = 1; o < 32; o <<= 1) {
            int t = __shfl_up_sync(0xFFFFFFFFu, w, o);
            if (lane >= o) w += t;
        }
        wsum[lane] = w;
    }
    __syncthreads();
    int base = v - s + (wd > 0 ? wsum[wd - 1] : 0);
    for (int i = lo; i < hi; i++) {
        g_off[i] = base;
        g_cur[i] = base;
        base += g_deg[i];
    }
    if (tid < 128) g_gsum[tid] = 0.f;
}

__global__ void k_scatter(const int* __restrict__ src, const int* __restrict__ dst, int e) {
    int i = blockIdx.x * blockDim.x + threadIdx.x;
    if (i < e) {
        int pos = atomicAdd(&g_cur[dst[i]], 1);
        g_elist[pos] = src[i];
    }
}

// ---------------------------------------------------------------------------
// Gather: warp per node d. pooled[d] = mean over edges of relu(a[src]+b[d]).
// a block = g_Y cols 128..255, b block = cols 256..383.
// ---------------------------------------------------------------------------
__global__ void __launch_bounds__(256) k_gather(int n) {
    int w = (blockIdx.x * blockDim.x + threadIdx.x) >> 5;
    if (w >= n) return;
    int lane = threadIdx.x & 31;
    int off = g_off[w], deg = g_deg[w];

    const float4* Y4 = (const float4*)g_Y;
    float4 vb = __ldg(Y4 + (size_t)w * 128 + 64 + lane);
    float ax = 0.f, ay = 0.f, az = 0.f, aw = 0.f;

    int s = (deg > 0) ? g_elist[off] : 0;
    for (int j = 0; j < deg; j++) {
        int s2 = (j + 1 < deg) ? g_elist[off + j + 1] : 0;
        float4 va = __ldg(Y4 + (size_t)s * 128 + 32 + lane);
        ax += fmaxf(va.x + vb.x, 0.f);
        ay += fmaxf(va.y + vb.y, 0.f);
        az += fmaxf(va.z + vb.z, 0.f);
        aw += fmaxf(va.w + vb.w, 0.f);
        s = s2;
    }
    float rc = 1.0f / (float)max(deg, 1);
    float4 o = make_float4(ax * rc, ay * rc, az * rc, aw * rc);
    ((float4*)g_pool)[(size_t)w * 32 + lane] = o;
}

// ---------------------------------------------------------------------------
// Fused relu + LayerNorm + graph mean-pool partial sums. Warp per row.
// ---------------------------------------------------------------------------
__global__ void __launch_bounds__(256) k_ln(const float* __restrict__ gamma,
                                            const float* __restrict__ beta, int n) {
    __shared__ float sacc[8][128];
    int lane = threadIdx.x & 31;
    int w = threadIdx.x >> 5;
    int gw = blockIdx.x * 8 + w;
    int nw = gridDim.x * 8;

    float4 ga = ((const float4*)gamma)[lane];
    float4 be = ((const float4*)beta)[lane];
    float ax = 0.f, ay = 0.f, az = 0.f, aw = 0.f;

    for (int row = gw; row < n; row += nw) {
        const float4* yr = ((const float4*)g_Y) + (size_t)row * 128;
        float4 h0 = __ldg(yr + lane);        // h0 block
        float4 cv = __ldg(yr + 96 + lane);   // c  block
        float4 up = __ldg(((const float4*)g_upd) + (size_t)row * 32 + lane);
        float vx = fmaxf(h0.x + cv.x + up.x, 0.f);
        float vy = fmaxf(h0.y + cv.y + up.y, 0.f);
        float vz = fmaxf(h0.z + cv.z + up.z, 0.f);
        float vw = fmaxf(h0.w + cv.w + up.w, 0.f);

        float s1 = vx + vy + vz + vw;
        float s2 = vx * vx + vy * vy + vz * vz + vw * vw;
        #pragma unroll
        for (int o = 16; o > 0; o >>= 1) {
            s1 += __shfl_xor_sync(0xFFFFFFFFu, s1, o);
            s2 += __shfl_xor_sync(0xFFFFFFFFu, s2, o);
        }
        float mu  = s1 * (1.f / 128.f);
        float var = s2 * (1.f / 128.f) - mu * mu;
        float is  = rsqrtf(var + 1e-6f);
        ax += (vx - mu) * is * ga.x + be.x;
        ay += (vy - mu) * is * ga.y + be.y;
        az += (vz - mu) * is * ga.z + be.z;
        aw += (vw - mu) * is * ga.w + be.w;
    }

    sacc[w][lane * 4 + 0] = ax;
    sacc[w][lane * 4 + 1] = ay;
    sacc[w][lane * 4 + 2] = az;
    sacc[w][lane * 4 + 3] = aw;
    __syncthreads();
    int t = threadIdx.x;
    if (t < 128) {
        float s = 0.f;
        #pragma unroll
        for (int ww = 0; ww < 8; ww++) s += sacc[ww][t];
        atomicAdd(&g_gsum[t], s);
    }
}

// ---------------------------------------------------------------------------
__global__ void k_final(const float* __restrict__ Wd, const float* __restrict__ bd,
                        float* __restrict__ out, int n) {
    int o = threadIdx.x;
    if (o >= 32) return;
    float s = 0.f;
    #pragma unroll
    for (int c = 0; c < 128; c++) s += g_gsum[c] * Wd[c * 32 + o];
    out[o] = s / (float)n + bd[o];
}

// ---------------------------------------------------------------------------
extern "C" void kernel_launch(void* const* d_in, const int* in_sizes, int n_in,
                              void* d_out, int out_size) {
    const float* x     = (const float*)d_in[0];
    const int*   esrc  = (const int*)d_in[1];
    const int*   edst  = (const int*)d_in[2];
    const float* Wp    = (const float*)d_in[3];
    const float* bp    = (const float*)d_in[4];
    const float* Wm    = (const float*)d_in[5];
    const float* bm    = (const float*)d_in[6];
    const float* Wu    = (const float*)d_in[7];
    const float* bu    = (const float*)d_in[8];
    const float* gamma = (const float*)d_in[9];
    const float* beta  = (const float*)d_in[10];
    const float* Wd    = (const float*)d_in[11];
    const float* bd    = (const float*)d_in[12];
    float* out = (float*)d_out;

    int n = in_sizes[0] / 128;
    int e = in_sizes[1];
    int rb = (n + 127) / 128;

    cudaFuncSetAttribute(k_gemm_h, cudaFuncAttributeMaxDynamicSharedMemorySize, GSM_SZ);

    k_zero<<<(n + 255) / 256, 256>>>(n);
    k_prep<<<256, 256>>>(Wp, bp, Wm, bm, Wu);
    // Y = x @ W3 + b3  -> h0 | a | b | c
    k_gemm_h<<<dim3(4, rb), 256, GSM_SZ>>>(x, nullptr, nullptr, n, 0);
    // CSR build + gather (segment mean)
    k_hist<<<(e + 255) / 256, 256>>>(edst, e);
    k_scan<<<1, 1024>>>(n);
    k_scatter<<<(e + 255) / 256, 256>>>(esrc, edst, e);
    k_gather<<<(n * 32 + 255) / 256, 256>>>(n);
    // upd = pooled @ WuB + bu
    k_gemm_h<<<dim3(1, rb), 256, GSM_SZ>>>(nullptr, Wu + 16384, bu, n, 1);
    // relu + LN + graph pool
    k_ln<<<1024, 256>>>(gamma, beta, n);
    k_final<<<1, 32>>>(Wd, bd, out, n);
}